// round 12
// baseline (speedup 1.0000x reference)
#include <cuda_runtime.h>
#include <stdint.h>

// PointPillars BEV scatter: (M,3) coords + (M,64) features -> (B,64,496,432)
#define BEV_H   496
#define BEV_W   432
#define NB      4
#define NC      64
#define HW      (BEV_H * BEV_W)        // 214272 cells per batch image
#define HW4     (HW / 4)               // 53568 float4-cells per batch image
#define NCELL4  (NB * HW4)             // 214272 float4-cells total
#define CPT     16                     // channels per thread
#define CPB     64                     // float4-cells per block (block = 64*4 = 256)
#define NBLK    (NCELL4 / CPB)         // 3348 blocks, exact (53568 % 64 == 0)

// Inverse map: raveled cell -> pillar index + 1 (0 = empty). 3.43 MB.
// Zero at module load; clear_idx_kernel re-zeroes exactly the occupied
// entries after each gather, so the map is all-zero again at end of call.
__device__ int g_map[NB * HW];

// ---------------------------------------------------------------------------
// Kernel 1: scatter pillar index+1 into the map (coords are collision-free).
__global__ void scatter_idx_kernel(const int* __restrict__ coords, int M) {
    int m = blockIdx.x * blockDim.x + threadIdx.x;
    if (m < M) {
        int b = coords[3 * m + 0];
        int y = coords[3 * m + 1];
        int x = coords[3 * m + 2];
        g_map[(b * BEV_H + y) * BEV_W + x] = m + 1;
    }
}

// ---------------------------------------------------------------------------
// Kernel 2: barrier-free register-transpose gather, channel-split 4 ways.
// t&63 -> float4-cell within block span, t>>6 -> channel group (16 ch).
// Flat addressing: float4-cell i covers g_map[4i..4i+3]; blocks never
// straddle a batch (HW4 % CPB == 0), so b is uniform per block.
// Per-quad interleaved load/transpose/store keeps the live set at 4 float4
// (regs ~32 -> 6 blocks/SM). All stores are STG.128 (512 B/warp), streaming.
__global__ __launch_bounds__(256, 6) void gather_kernel(
    const float* __restrict__ feat, float* __restrict__ out) {
    const int t    = threadIdx.x;
    const int cg   = t >> 6;                       // 0..3
    const int cell = blockIdx.x * CPB + (t & 63);  // global float4-cell

    const int4 mp = __ldg(reinterpret_cast<const int4*>(&g_map[4 * cell]));

    const float4* f0 = mp.x ? reinterpret_cast<const float4*>(
        feat + (size_t)(mp.x - 1) * NC + cg * CPT) : nullptr;
    const float4* f1 = mp.y ? reinterpret_cast<const float4*>(
        feat + (size_t)(mp.y - 1) * NC + cg * CPT) : nullptr;
    const float4* f2 = mp.z ? reinterpret_cast<const float4*>(
        feat + (size_t)(mp.z - 1) * NC + cg * CPT) : nullptr;
    const float4* f3 = mp.w ? reinterpret_cast<const float4*>(
        feat + (size_t)(mp.w - 1) * NC + cg * CPT) : nullptr;

    const int b = (4 * cell) / HW;                 // uniform per block
    float* outp = out + ((size_t)(b * NC + cg * CPT)) * HW + (4 * cell - b * HW);
    const size_t cs = (size_t)HW;
    const float4 z = make_float4(0.f, 0.f, 0.f, 0.f);

#pragma unroll
    for (int q = 0; q < 4; ++q) {
        const float4 a = f0 ? f0[q] : z;
        const float4 c = f1 ? f1[q] : z;
        const float4 d = f2 ? f2[q] : z;
        const float4 e = f3 ? f3[q] : z;
        __stcs(reinterpret_cast<float4*>(outp), make_float4(a.x, c.x, d.x, e.x));
        outp += cs;
        __stcs(reinterpret_cast<float4*>(outp), make_float4(a.y, c.y, d.y, e.y));
        outp += cs;
        __stcs(reinterpret_cast<float4*>(outp), make_float4(a.z, c.z, d.z, e.z));
        outp += cs;
        __stcs(reinterpret_cast<float4*>(outp), make_float4(a.w, c.w, d.w, e.w));
        outp += cs;
    }
}

// ---------------------------------------------------------------------------
// Kernel 3: re-zero exactly the occupied map entries (runs after gather).
__global__ void clear_idx_kernel(const int* __restrict__ coords, int M) {
    int m = blockIdx.x * blockDim.x + threadIdx.x;
    if (m < M) {
        int b = coords[3 * m + 0];
        int y = coords[3 * m + 1];
        int x = coords[3 * m + 2];
        g_map[(b * BEV_H + y) * BEV_W + x] = 0;
    }
}

// ---------------------------------------------------------------------------
extern "C" void kernel_launch(void* const* d_in, const int* in_sizes, int n_in,
                              void* d_out, int out_size) {
    const int*   coords = (const int*)d_in[0];    // (M, 3) int32
    const float* feat   = (const float*)d_in[1];  // (M, 64) float32
    float*       out    = (float*)d_out;          // (4, 64, 496, 432) float32
    const int M = in_sizes[0] / 3;

    scatter_idx_kernel<<<(M + 255) / 256, 256>>>(coords, M);
    gather_kernel<<<NBLK, 256>>>(feat, out);
    clear_idx_kernel<<<(M + 255) / 256, 256>>>(coords, M);
}